// round 6
// baseline (speedup 1.0000x reference)
#include <cuda_runtime.h>
#include <cuda_bf16.h>
#include <math_constants.h>

// AttentionMax: correlation[b,s] = <q[b], sub[b,s]>, argmax over s, one-hot out [bz, ns, 1]
// bz=4096, ns=256, d=128, fp32. Memory-bound: 512MB stream of feat_sub.
//
// R6: one WARP per batch element. No smem, no __syncthreads, no block argmax,
// single wave (1024 CTAs x 128 thr, 8 CTAs/SM). Warps fully decoupled; tests
// whether R2-R5's stable 85% DRAM was block-coupling overhead or chip ceiling.

#define NS 256
#define D  128

// Fold 4 rows' per-lane partials into full row sums.
// Result: lane L holds sum of row base + ((L>>3)&3), replicated across 8 lanes.
__device__ __forceinline__ float reduce4(float p0, float p1, float p2, float p3,
                                         int lane)
{
    const unsigned FULL = 0xffffffffu;
    bool hi16 = (lane & 16) != 0;
    float s0 = hi16 ? p0 : p2;
    float s1 = hi16 ? p1 : p3;
    float r0 = __shfl_xor_sync(FULL, s0, 16);
    float r1 = __shfl_xor_sync(FULL, s1, 16);
    float a0 = (hi16 ? p2 : p0) + r0;
    float a1 = (hi16 ? p3 : p1) + r1;
    bool hi8 = (lane & 8) != 0;
    float s = hi8 ? a0 : a1;
    float r = __shfl_xor_sync(FULL, s, 8);
    float acc = (hi8 ? a1 : a0) + r;
    acc += __shfl_xor_sync(FULL, acc, 4);
    acc += __shfl_xor_sync(FULL, acc, 2);
    acc += __shfl_xor_sync(FULL, acc, 1);
    return acc;
}

__device__ __forceinline__ float dot4(float4 v, float4 q)
{
    float p = v.x * q.x;
    p = fmaf(v.y, q.y, p);
    p = fmaf(v.z, q.z, p);
    p = fmaf(v.w, q.w, p);
    return p;
}

__global__ __launch_bounds__(128, 8)
void attention_max_kernel(const float* __restrict__ q,
                          const float* __restrict__ sub,
                          float* __restrict__ out,
                          int bz)
{
    const int lane = threadIdx.x & 31;
    const int b    = blockIdx.x * 4 + (threadIdx.x >> 5);  // warp -> batch
    if (b >= bz) return;

    const int myrow = (lane >> 3) & 3;
    const unsigned FULL = 0xffffffffu;

    // Query chunk for this lane (stays in registers; coalesced per warp).
    const float4 qc = reinterpret_cast<const float4*>(q + (size_t)b * D)[lane];

    // This warp streams all 256 rows of its batch.
    const float4* base = reinterpret_cast<const float4*>(sub + (size_t)b * NS * D);

    float bestv = -CUDART_INF_F;
    int   besti = 0;

    float4 va[4], vb[4];
#pragma unroll
    for (int j = 0; j < 4; ++j)
        va[j] = __ldcs(&base[j * 32 + lane]);

#pragma unroll 2
    for (int rr = 0; rr < NS; rr += 8) {
        // prefetch rows rr+4..rr+7 while reducing rr..rr+3
#pragma unroll
        for (int j = 0; j < 4; ++j)
            vb[j] = __ldcs(&base[(rr + 4 + j) * 32 + lane]);

        {
            float s = reduce4(dot4(va[0], qc), dot4(va[1], qc),
                              dot4(va[2], qc), dot4(va[3], qc), lane);
            if (s > bestv) { bestv = s; besti = rr + myrow; }
        }

        if (rr + 8 < NS) {
#pragma unroll
            for (int j = 0; j < 4; ++j)
                va[j] = __ldcs(&base[(rr + 8 + j) * 32 + lane]);
        }

        {
            float s = reduce4(dot4(vb[0], qc), dot4(vb[1], qc),
                              dot4(vb[2], qc), dot4(vb[3], qc), lane);
            if (s > bestv) { bestv = s; besti = rr + 4 + myrow; }
        }
    }

    // Warp argmax (value max, smaller index wins ties -> first occurrence).
#pragma unroll
    for (int m = 16; m > 0; m >>= 1) {
        float ov = __shfl_xor_sync(FULL, bestv, m);
        int   oi = __shfl_xor_sync(FULL, besti, m);
        if (ov > bestv || (ov == bestv && oi < besti)) { bestv = ov; besti = oi; }
    }

    // One-hot write: warp owns out[b*256 .. b*256+255]; 2 float4 per lane.
    float4* orow = reinterpret_cast<float4*>(out + (size_t)b * NS);
#pragma unroll
    for (int k = 0; k < 2; ++k) {
        int e = (k * 32 + lane) * 4;     // first element of this float4
        float4 v;
        v.x = (e + 0 == besti) ? 1.0f : 0.0f;
        v.y = (e + 1 == besti) ? 1.0f : 0.0f;
        v.z = (e + 2 == besti) ? 1.0f : 0.0f;
        v.w = (e + 3 == besti) ? 1.0f : 0.0f;
        orow[k * 32 + lane] = v;
    }
}

extern "C" void kernel_launch(void* const* d_in, const int* in_sizes, int n_in,
                              void* d_out, int out_size)
{
    const float* q   = (const float*)d_in[0];   // [4096, 128]
    const float* sub = (const float*)d_in[1];   // [4096, 256, 128]
    float*       out = (float*)d_out;           // [4096, 256, 1]

    const int bz = in_sizes[0] / D;             // 4096

    const int grid = (bz + 3) / 4;              // 4 warps (batches) per CTA
    attention_max_kernel<<<grid, 128>>>(q, sub, out, bz);
}